// round 12
// baseline (speedup 1.0000x reference)
#include <cuda_runtime.h>
#include <cstdint>

#define Bsz 2048
#define Tlen 512
#define Ktag 32
#define FULLMASK 0xFFFFFFFFu
#define STRIDE (Bsz * Ktag)

// Per-step alpha rows (exact); recomputed-argmax backtrace reads these.
__device__ float g_alpha[(size_t)Tlen * Bsz * Ktag];   // 134 MB
__device__ int   g_perm[Bsz];                          // length-sorted order
__device__ int   g_lastTag[Bsz];

union f2u { float2 f; unsigned long long u; };

__device__ __forceinline__ unsigned long long add2(unsigned long long a, unsigned long long b) {
    unsigned long long r; asm("add.rn.f32x2 %0,%1,%2;" : "=l"(r) : "l"(a), "l"(b)); return r;
}
__device__ __forceinline__ unsigned long long pfma2(unsigned long long a, unsigned long long b, unsigned long long c) {
    unsigned long long r; asm("fma.rn.f32x2 %0,%1,%2,%3;" : "=l"(r) : "l"(a), "l"(b), "l"(c)); return r;
}
// order-preserving float->uint bijection (no NaNs in this problem)
__device__ __forceinline__ unsigned ordf(float s) {
    int b = __float_as_int(s);
    return (unsigned)(b ^ ((b >> 31) | 0x80000000));
}
// compiler-only ordering fence (warp converged; smem in-order per warp)
__device__ __forceinline__ void cfence() { asm volatile("" ::: "memory"); }

// ---------------------------------------------------------------------------
// Kernel 0: counting sort by length -> g_perm. One block, 1024 threads.
// ---------------------------------------------------------------------------
__global__ void crf_sort(const int* __restrict__ slen)
{
    __shared__ int hist[512];
    __shared__ int wsum[16];
    const int tid  = threadIdx.x;
    const int lane = tid & 31, wid = tid >> 5;

    for (int i = tid; i < 512; i += 1024) hist[i] = 0;
    __syncthreads();
    for (int b = tid; b < Bsz; b += 1024) atomicAdd(&hist[slen[b] - 1], 1);
    __syncthreads();

    int v = 0, s = 0;
    if (tid < 512) {
        v = hist[tid];
        s = v;
#pragma unroll
        for (int off = 1; off < 32; off <<= 1) {
            int u = __shfl_up_sync(FULLMASK, s, off);
            if (lane >= off) s += u;
        }
        if (lane == 31) wsum[wid] = s;
    }
    __syncthreads();
    if (tid < 16) {
        int t = wsum[tid], ss = t;
#pragma unroll
        for (int off = 1; off < 16; off <<= 1) {
            int u = __shfl_up_sync(0xFFFFu, ss, off);
            if (tid >= off) ss += u;
        }
        wsum[tid] = ss - t;
    }
    __syncthreads();
    if (tid < 512) hist[tid] = (s - v) + wsum[wid];
    __syncthreads();
    for (int b = tid; b < Bsz; b += 1024) {
        int pos = atomicAdd(&hist[slen[b] - 1], 1);
        g_perm[pos] = b;
    }
}

// ---------------------------------------------------------------------------
// Kernel 1 (FORWARD ONLY): one warp per block, 2 length-balanced tasks/warp.
// Blocks [0,1024):    Viterbi forward on (perm[w], perm[2047-w]);
//                     stores alphas, best_score, tail tags, lastTag.
// Blocks [1024,2048): logsumexp forward + sequence score + loglik, same pairs.
// Equal spans for all warps -> no retirement tail; no latency-bound phases.
// ---------------------------------------------------------------------------
__global__ __launch_bounds__(32, 32)
void crf_fwd(const float* __restrict__ pot,
             const float* __restrict__ trans,
             const int*   __restrict__ slen,
             const int*   __restrict__ tg_in,
             float*       __restrict__ out)
{
    __shared__ __align__(16) float buf[2][32];
    const int w = blockIdx.x;
    const int j = threadIdx.x;

    if (w < Bsz / 2) {
        // ============================ VITERBI ============================
        f2u Tp[16];                                  // packed rows (2q,2q+1), col j
#pragma unroll
        for (int q = 0; q < 16; ++q) {
            Tp[q].f.x = __ldg(&trans[(2 * q) * 32 + j]);
            Tp[q].f.y = __ldg(&trans[(2 * q + 1) * 32 + j]);
        }
        __syncwarp();

#pragma unroll 1
        for (int task = 0; task < 2; ++task) {
            const int b = g_perm[task ? (Bsz - 1 - w) : w];
            const int L = slen[b];
            const float* p = pot + (size_t)b * Tlen * Ktag + j;
            float* aSt = g_alpha + (size_t)b * Ktag + j;

            float alpha = __ldg(p);                  // t = 0

            auto step = [&](float pcv, int t) {
                buf[t & 1][j] = alpha;
                aSt[(size_t)(t - 1) * STRIDE] = alpha;   // save for backtrace
                cfence();                                // converged-warp broadcast
                const ulonglong2* A = (const ulonglong2*)buf[t & 1];
                float m0 = -3.4e38f, m1 = -3.4e38f, m2 = -3.4e38f, m3 = -3.4e38f;
#pragma unroll
                for (int g = 0; g < 8; ++g) {
                    const ulonglong2 av = A[g];
                    f2u s0, s1;
                    s0.u = add2(av.x, Tp[2 * g].u);
                    s1.u = add2(av.y, Tp[2 * g + 1].u);
                    m0 = fmaxf(m0, s0.f.x); m1 = fmaxf(m1, s0.f.y);
                    m2 = fmaxf(m2, s1.f.x); m3 = fmaxf(m3, s1.f.y);
                }
                alpha = pcv + fmaxf(fmaxf(m0, m1), fmaxf(m2, m3));
            };

            // clamped initial prefetch; unclamped refills inside guarded loop
            float q0 = __ldg(p + (size_t)min(1, L - 1) * Ktag);
            float q1 = __ldg(p + (size_t)min(2, L - 1) * Ktag);
            float q2 = __ldg(p + (size_t)min(3, L - 1) * Ktag);
            float q3 = __ldg(p + (size_t)min(4, L - 1) * Ktag);
            float q4 = __ldg(p + (size_t)min(5, L - 1) * Ktag);
            float q5 = __ldg(p + (size_t)min(6, L - 1) * Ktag);
            float q6 = __ldg(p + (size_t)min(7, L - 1) * Ktag);
            float q7 = __ldg(p + (size_t)min(8, L - 1) * Ktag);
            int t = 1;
#pragma unroll 1
            for (; t + 16 <= L; t += 8) {            // refill idx <= t+15 <= L-1
                step(q0, t + 0); q0 = __ldg(p + (size_t)(t + 8) * Ktag);
                step(q1, t + 1); q1 = __ldg(p + (size_t)(t + 9) * Ktag);
                step(q2, t + 2); q2 = __ldg(p + (size_t)(t + 10) * Ktag);
                step(q3, t + 3); q3 = __ldg(p + (size_t)(t + 11) * Ktag);
                step(q4, t + 4); q4 = __ldg(p + (size_t)(t + 12) * Ktag);
                step(q5, t + 5); q5 = __ldg(p + (size_t)(t + 13) * Ktag);
                step(q6, t + 6); q6 = __ldg(p + (size_t)(t + 14) * Ktag);
                step(q7, t + 7); q7 = __ldg(p + (size_t)(t + 15) * Ktag);
            }
#pragma unroll 1
            for (; t < L; ++t) step(__ldg(p + (size_t)t * Ktag), t);  // L1 hits

            // final max/argmax (first-max) via redux + ballot
            const unsigned ua = ordf(alpha);
            const unsigned um = __reduce_max_sync(FULLMASK, ua);
            const int idx = __ffs((int)__ballot_sync(FULLMASK, ua == um)) - 1;
            const float v = __shfl_sync(FULLMASK, alpha, idx);
            if (j == 0) {
                out[(size_t)Bsz * Tlen + b] = v;     // best_score
                g_lastTag[b] = idx;
            }

            float* tagOut = out + (size_t)b * Tlen;
            for (int tt = L - 1 + j; tt < Tlen; tt += 32)
                tagOut[tt] = (float)idx;             // tail = last tag
        }
    } else {
        // ========================== LOGSUMEXP + SCORE ==========================
        const int w2 = w - Bsz / 2;
        f2u Ep[16];
#pragma unroll
        for (int q = 0; q < 16; ++q) {
            Ep[q].f.x = expf(__ldg(&trans[(2 * q) * 32 + j]));
            Ep[q].f.y = expf(__ldg(&trans[(2 * q + 1) * 32 + j]));
        }

#pragma unroll 1
        for (int task = 0; task < 2; ++task) {
            const int b = g_perm[task ? (Bsz - 1 - w2) : w2];
            const int L = slen[b];
            const float* p = pot + (size_t)b * Tlen * Ktag + j;

            float alpha = __ldg(p);

            auto step = [&](float pcv, int t) {
                // shift by lane0 alpha: intra-step spread bounded, fp32-safe
                const float m = __shfl_sync(FULLMASK, alpha, 0);
                const float e = __expf(alpha - m);
                buf[t & 1][j] = e;
                cfence();                            // converged-warp broadcast
                const ulonglong2* A = (const ulonglong2*)buf[t & 1];
                f2u a0, a1, a2, a3;
                a0.u = 0ull; a1.u = 0ull; a2.u = 0ull; a3.u = 0ull;
#pragma unroll
                for (int g = 0; g < 8; g += 2) {     // 4 packed accs, 4 deep
                    const ulonglong2 av0 = A[g];
                    const ulonglong2 av1 = A[g + 1];
                    a0.u = pfma2(av0.x, Ep[2 * g].u,     a0.u);
                    a1.u = pfma2(av0.y, Ep[2 * g + 1].u, a1.u);
                    a2.u = pfma2(av1.x, Ep[2 * g + 2].u, a2.u);
                    a3.u = pfma2(av1.y, Ep[2 * g + 3].u, a3.u);
                }
                a0.u = add2(a0.u, a1.u);
                a2.u = add2(a2.u, a3.u);
                a0.u = add2(a0.u, a2.u);
                alpha = pcv + m + __logf(a0.f.x + a0.f.y);
            };

            float q0 = __ldg(p + (size_t)min(1, L - 1) * Ktag);
            float q1 = __ldg(p + (size_t)min(2, L - 1) * Ktag);
            float q2 = __ldg(p + (size_t)min(3, L - 1) * Ktag);
            float q3 = __ldg(p + (size_t)min(4, L - 1) * Ktag);
            float q4 = __ldg(p + (size_t)min(5, L - 1) * Ktag);
            float q5 = __ldg(p + (size_t)min(6, L - 1) * Ktag);
            float q6 = __ldg(p + (size_t)min(7, L - 1) * Ktag);
            float q7 = __ldg(p + (size_t)min(8, L - 1) * Ktag);
            int t = 1;
#pragma unroll 1
            for (; t + 16 <= L; t += 8) {
                step(q0, t + 0); q0 = __ldg(p + (size_t)(t + 8) * Ktag);
                step(q1, t + 1); q1 = __ldg(p + (size_t)(t + 9) * Ktag);
                step(q2, t + 2); q2 = __ldg(p + (size_t)(t + 10) * Ktag);
                step(q3, t + 3); q3 = __ldg(p + (size_t)(t + 11) * Ktag);
                step(q4, t + 4); q4 = __ldg(p + (size_t)(t + 12) * Ktag);
                step(q5, t + 5); q5 = __ldg(p + (size_t)(t + 13) * Ktag);
                step(q6, t + 6); q6 = __ldg(p + (size_t)(t + 14) * Ktag);
                step(q7, t + 7); q7 = __ldg(p + (size_t)(t + 15) * Ktag);
            }
#pragma unroll 1
            for (; t < L; ++t) step(__ldg(p + (size_t)t * Ktag), t);

            // final logsumexp over lanes
            float mm = alpha;
#pragma unroll
            for (int off = 16; off; off >>= 1)
                mm = fmaxf(mm, __shfl_xor_sync(FULLMASK, mm, off));
            float e = __expf(alpha - mm);
#pragma unroll
            for (int off = 16; off; off >>= 1)
                e += __shfl_xor_sync(FULLMASK, e, off);
            const float logNorm = mm + __logf(e);

            // sequence score + log-likelihood
            const int*   tg = tg_in + (size_t)b * Tlen;
            const float* p0 = pot + (size_t)b * Tlen * Ktag;
            float s = 0.f;
            for (int t2 = j; t2 < L; t2 += 32) {
                const int tt = tg[t2];
                s += __ldg(&p0[t2 * Ktag + tt]);
                if (t2 < L - 1) s += __ldg(&trans[tt * 32 + tg[t2 + 1]]);
            }
#pragma unroll
            for (int off = 16; off; off >>= 1)
                s += __shfl_xor_sync(FULLMASK, s, off);
            if (j == 0)
                out[(size_t)Bsz * Tlen + Bsz + b] = s - logNorm;
        }
    }
}

// ---------------------------------------------------------------------------
// Kernel 2 (BACKTRACE): one warp per batch, latency-bound chain, all 2048
// warps fully concurrent (14/SM) -> wall ~ max-L chain only.
// ---------------------------------------------------------------------------
__global__ __launch_bounds__(32, 32)
void crf_bt(const float* __restrict__ trans,
            const int*   __restrict__ slen,
            float*       __restrict__ out)
{
    __shared__ float transS[32 * 33];               // [i][tag], pad 33
    const int b = blockIdx.x;
    const int j = threadIdx.x;

    const int L = slen[b];
    if (L < 2) return;                               // tail already written

    for (int q = j; q < 32 * 32; q += 32)
        transS[(q >> 5) * 33 + (q & 31)] = __ldg(&trans[q]);
    __syncwarp();

    const int idx = g_lastTag[b];
    const float* aSt = g_alpha + (size_t)b * Ktag + j;
    float* tagOut = out + (size_t)b * Tlen;

    int tag = idx;
    float myTag = 0.f;
    float cur[8], nxt[8];
    const int t0 = L - 1;
#pragma unroll
    for (int k = 0; k < 8; ++k) {
        const int tt = t0 - k;
        cur[k] = (tt >= 1) ? aSt[(size_t)(tt - 1) * STRIDE] : 0.f;
    }
#pragma unroll 1
    for (int tc = t0; tc >= 1; tc -= 8) {
#pragma unroll
        for (int k = 0; k < 8; ++k) {                // prefetch next chunk
            const int tt = tc - 8 - k;
            nxt[k] = (tt >= 1) ? aSt[(size_t)(tt - 1) * STRIDE] : 0.f;
        }
#pragma unroll
        for (int k = 0; k < 8; ++k) {
            const int tt = tc - k;
            if (tt >= 1) {
                const float s = cur[k] + transS[j * 33 + tag];
                const unsigned u = ordf(s);
                const unsigned mm = __reduce_max_sync(FULLMASK, u);
                const int prev = __ffs((int)__ballot_sync(FULLMASK, u == mm)) - 1;
                const int pos = tt - 1;
                if ((pos & 31) == j) myTag = (float)prev;
                if ((pos & 31) == 0 && pos + j <= L - 2)
                    tagOut[pos + j] = myTag;         // coalesced flush
                tag = prev;
            }
        }
#pragma unroll
        for (int k = 0; k < 8; ++k) cur[k] = nxt[k];
    }
}

// ---------------------------------------------------------------------------
extern "C" void kernel_launch(void* const* d_in, const int* in_sizes, int n_in,
                              void* d_out, int out_size)
{
    const float* pot   = (const float*)d_in[0];
    const float* trans = (const float*)d_in[1];
    const int*   slen  = (const int*)d_in[2];
    const int*   tags  = (const int*)d_in[3];
    float*       out   = (float*)d_out;

    crf_sort<<<1, 1024>>>(slen);
    crf_fwd<<<Bsz, 32>>>(pot, trans, slen, tags, out);
    crf_bt<<<Bsz, 32>>>(trans, slen, out);
}

// round 13
// speedup vs baseline: 1.2069x; 1.2069x over previous
#include <cuda_runtime.h>
#include <cstdint>

#define Bsz 2048
#define Tlen 512
#define Ktag 32
#define FULLMASK 0xFFFFFFFFu
#define STRIDE (Bsz * Ktag)

// Per-step alpha rows (exact); recomputed-argmax backtrace reads these.
__device__ float g_alpha[(size_t)Tlen * Bsz * Ktag];   // 134 MB
__device__ int   g_perm[Bsz];                          // length-sorted order

union f2u { float2 f; unsigned long long u; };

__device__ __forceinline__ unsigned long long add2(unsigned long long a, unsigned long long b) {
    unsigned long long r; asm("add.rn.f32x2 %0,%1,%2;" : "=l"(r) : "l"(a), "l"(b)); return r;
}
__device__ __forceinline__ unsigned long long pfma2(unsigned long long a, unsigned long long b, unsigned long long c) {
    unsigned long long r; asm("fma.rn.f32x2 %0,%1,%2,%3;" : "=l"(r) : "l"(a), "l"(b), "l"(c)); return r;
}
// order-preserving float->uint bijection (no NaNs in this problem)
__device__ __forceinline__ unsigned ordf(float s) {
    int b = __float_as_int(s);
    return (unsigned)(b ^ ((b >> 31) | 0x80000000));
}
// compiler-only ordering fence (warp converged; smem in-order per warp)
__device__ __forceinline__ void cfence() { asm volatile("" ::: "memory"); }

// ---------------------------------------------------------------------------
// Kernel 0: counting sort by length -> g_perm. One block, 1024 threads.
// ---------------------------------------------------------------------------
__global__ void crf_sort(const int* __restrict__ slen)
{
    __shared__ int hist[512];
    __shared__ int wsum[16];
    const int tid  = threadIdx.x;
    const int lane = tid & 31, wid = tid >> 5;

    for (int i = tid; i < 512; i += 1024) hist[i] = 0;
    __syncthreads();
    for (int b = tid; b < Bsz; b += 1024) atomicAdd(&hist[slen[b] - 1], 1);
    __syncthreads();

    int v = 0, s = 0;
    if (tid < 512) {
        v = hist[tid];
        s = v;
#pragma unroll
        for (int off = 1; off < 32; off <<= 1) {
            int u = __shfl_up_sync(FULLMASK, s, off);
            if (lane >= off) s += u;
        }
        if (lane == 31) wsum[wid] = s;
    }
    __syncthreads();
    if (tid < 16) {
        int t = wsum[tid], ss = t;
#pragma unroll
        for (int off = 1; off < 16; off <<= 1) {
            int u = __shfl_up_sync(0xFFFFu, ss, off);
            if (tid >= off) ss += u;
        }
        wsum[tid] = ss - t;
    }
    __syncthreads();
    if (tid < 512) hist[tid] = (s - v) + wsum[wid];
    __syncthreads();
    for (int b = tid; b < Bsz; b += 1024) {
        int pos = atomicAdd(&hist[slen[b] - 1], 1);
        g_perm[pos] = b;
    }
}

// ---------------------------------------------------------------------------
// Kernel 1: one warp per block, 2 length-balanced tasks per warp.
// Blocks [0,1024):    Viterbi, order fwd(A), bt(A), fwd(B), bt(B) so the
//                     latency-bound bt phases are time-staggered across warps
//                     (task-A lengths are the sorted ranks).
// Blocks [1024,2048): logsumexp + score on (perm[w], perm[2047-w]).
// ---------------------------------------------------------------------------
__global__ __launch_bounds__(32, 28)
void crf_main(const float* __restrict__ pot,
              const float* __restrict__ trans,
              const int*   __restrict__ slen,
              const int*   __restrict__ tg_in,
              float*       __restrict__ out)
{
    __shared__ __align__(16) float buf[2][32];
    __shared__ float transS[32 * 33];               // [i][tag], pad 33
    const int w = blockIdx.x;
    const int j = threadIdx.x;

    if (w < Bsz / 2) {
        // ============================ VITERBI ============================
        f2u Tp[16];                                  // packed rows (2q,2q+1), col j
#pragma unroll
        for (int q = 0; q < 16; ++q) {
            Tp[q].f.x = __ldg(&trans[(2 * q) * 32 + j]);
            Tp[q].f.y = __ldg(&trans[(2 * q + 1) * 32 + j]);
        }
        for (int q = j; q < 32 * 32; q += 32)       // transS[i*33+c] = T[i][c]
            transS[(q >> 5) * 33 + (q & 31)] = __ldg(&trans[q]);
        __syncwarp();

#pragma unroll 1
        for (int task = 0; task < 2; ++task) {
            const int b = g_perm[task ? (Bsz - 1 - w) : w];
            const int L = slen[b];
            const float* p = pot + (size_t)b * Tlen * Ktag + j;
            float* aSt = g_alpha + (size_t)b * Ktag + j;

            // ----------------------- forward -----------------------
            float alpha = __ldg(p);                  // t = 0

            auto step = [&](float pcv, int t) {
                buf[t & 1][j] = alpha;
                aSt[(size_t)(t - 1) * STRIDE] = alpha;   // save for backtrace
                cfence();                                // converged-warp broadcast
                const ulonglong2* A = (const ulonglong2*)buf[t & 1];
                float m0 = -3.4e38f, m1 = -3.4e38f, m2 = -3.4e38f, m3 = -3.4e38f;
#pragma unroll
                for (int g = 0; g < 8; ++g) {
                    const ulonglong2 av = A[g];
                    f2u s0, s1;
                    s0.u = add2(av.x, Tp[2 * g].u);
                    s1.u = add2(av.y, Tp[2 * g + 1].u);
                    m0 = fmaxf(m0, s0.f.x); m1 = fmaxf(m1, s0.f.y);
                    m2 = fmaxf(m2, s1.f.x); m3 = fmaxf(m3, s1.f.y);
                }
                alpha = pcv + fmaxf(fmaxf(m0, m1), fmaxf(m2, m3));
            };

            // clamped initial prefetch; unclamped refills inside guarded loop
            float q0 = __ldg(p + (size_t)min(1, L - 1) * Ktag);
            float q1 = __ldg(p + (size_t)min(2, L - 1) * Ktag);
            float q2 = __ldg(p + (size_t)min(3, L - 1) * Ktag);
            float q3 = __ldg(p + (size_t)min(4, L - 1) * Ktag);
            float q4 = __ldg(p + (size_t)min(5, L - 1) * Ktag);
            float q5 = __ldg(p + (size_t)min(6, L - 1) * Ktag);
            float q6 = __ldg(p + (size_t)min(7, L - 1) * Ktag);
            float q7 = __ldg(p + (size_t)min(8, L - 1) * Ktag);
            int t = 1;
#pragma unroll 1
            for (; t + 16 <= L; t += 8) {            // refill idx <= t+15 <= L-1
                step(q0, t + 0); q0 = __ldg(p + (size_t)(t + 8) * Ktag);
                step(q1, t + 1); q1 = __ldg(p + (size_t)(t + 9) * Ktag);
                step(q2, t + 2); q2 = __ldg(p + (size_t)(t + 10) * Ktag);
                step(q3, t + 3); q3 = __ldg(p + (size_t)(t + 11) * Ktag);
                step(q4, t + 4); q4 = __ldg(p + (size_t)(t + 12) * Ktag);
                step(q5, t + 5); q5 = __ldg(p + (size_t)(t + 13) * Ktag);
                step(q6, t + 6); q6 = __ldg(p + (size_t)(t + 14) * Ktag);
                step(q7, t + 7); q7 = __ldg(p + (size_t)(t + 15) * Ktag);
            }
#pragma unroll 1
            for (; t < L; ++t) step(__ldg(p + (size_t)t * Ktag), t);  // L1 hits

            // final max/argmax (first-max) via redux + ballot
            const unsigned ua = ordf(alpha);
            const unsigned um = __reduce_max_sync(FULLMASK, ua);
            const int idx = __ffs((int)__ballot_sync(FULLMASK, ua == um)) - 1;
            const float v = __shfl_sync(FULLMASK, alpha, idx);
            if (j == 0) out[(size_t)Bsz * Tlen + b] = v;     // best_score

            float* tagOut = out + (size_t)b * Tlen;
            for (int tt = L - 1 + j; tt < Tlen; tt += 32)
                tagOut[tt] = (float)idx;                     // tail = last tag

            // ------------- backtrace (immediately, staggered) -------------
            if (L >= 2) {
                int tag = idx;
                float myTag = 0.f;
                float cur[8], nxt[8];
                const int t0 = L - 1;
#pragma unroll
                for (int k = 0; k < 8; ++k) {
                    const int tt = t0 - k;
                    cur[k] = (tt >= 1) ? aSt[(size_t)(tt - 1) * STRIDE] : 0.f;
                }
#pragma unroll 1
                for (int tc = t0; tc >= 1; tc -= 8) {
#pragma unroll
                    for (int k = 0; k < 8; ++k) {            // prefetch next chunk
                        const int tt = tc - 8 - k;
                        nxt[k] = (tt >= 1) ? aSt[(size_t)(tt - 1) * STRIDE] : 0.f;
                    }
#pragma unroll
                    for (int k = 0; k < 8; ++k) {
                        const int tt = tc - k;
                        if (tt >= 1) {
                            const float s = cur[k] + transS[j * 33 + tag];
                            const unsigned u = ordf(s);
                            const unsigned mm = __reduce_max_sync(FULLMASK, u);
                            const int prev = __ffs((int)__ballot_sync(FULLMASK, u == mm)) - 1;
                            const int pos = tt - 1;
                            if ((pos & 31) == j) myTag = (float)prev;
                            if ((pos & 31) == 0 && pos + j <= L - 2)
                                tagOut[pos + j] = myTag;     // coalesced flush
                            tag = prev;
                        }
                    }
#pragma unroll
                    for (int k = 0; k < 8; ++k) cur[k] = nxt[k];
                }
            }
        }
    } else {
        // ========================== LOGSUMEXP + SCORE ==========================
        const int w2 = w - Bsz / 2;
        f2u Ep[16];
#pragma unroll
        for (int q = 0; q < 16; ++q) {
            Ep[q].f.x = expf(__ldg(&trans[(2 * q) * 32 + j]));
            Ep[q].f.y = expf(__ldg(&trans[(2 * q + 1) * 32 + j]));
        }

#pragma unroll 1
        for (int task = 0; task < 2; ++task) {
            const int b = g_perm[task ? (Bsz - 1 - w2) : w2];
            const int L = slen[b];
            const float* p = pot + (size_t)b * Tlen * Ktag + j;

            float alpha = __ldg(p);

            auto step = [&](float pcv, int t) {
                // shift by lane0 alpha: intra-step spread bounded, fp32-safe
                const float m = __shfl_sync(FULLMASK, alpha, 0);
                const float e = __expf(alpha - m);
                buf[t & 1][j] = e;
                cfence();                            // converged-warp broadcast
                const ulonglong2* A = (const ulonglong2*)buf[t & 1];
                f2u a0, a1, a2, a3;
                a0.u = 0ull; a1.u = 0ull; a2.u = 0ull; a3.u = 0ull;
#pragma unroll
                for (int g = 0; g < 8; g += 2) {     // 4 packed accs, 4 deep
                    const ulonglong2 av0 = A[g];
                    const ulonglong2 av1 = A[g + 1];
                    a0.u = pfma2(av0.x, Ep[2 * g].u,     a0.u);
                    a1.u = pfma2(av0.y, Ep[2 * g + 1].u, a1.u);
                    a2.u = pfma2(av1.x, Ep[2 * g + 2].u, a2.u);
                    a3.u = pfma2(av1.y, Ep[2 * g + 3].u, a3.u);
                }
                a0.u = add2(a0.u, a1.u);
                a2.u = add2(a2.u, a3.u);
                a0.u = add2(a0.u, a2.u);
                alpha = pcv + m + __logf(a0.f.x + a0.f.y);
            };

            float q0 = __ldg(p + (size_t)min(1, L - 1) * Ktag);
            float q1 = __ldg(p + (size_t)min(2, L - 1) * Ktag);
            float q2 = __ldg(p + (size_t)min(3, L - 1) * Ktag);
            float q3 = __ldg(p + (size_t)min(4, L - 1) * Ktag);
            float q4 = __ldg(p + (size_t)min(5, L - 1) * Ktag);
            float q5 = __ldg(p + (size_t)min(6, L - 1) * Ktag);
            float q6 = __ldg(p + (size_t)min(7, L - 1) * Ktag);
            float q7 = __ldg(p + (size_t)min(8, L - 1) * Ktag);
            int t = 1;
#pragma unroll 1
            for (; t + 16 <= L; t += 8) {
                step(q0, t + 0); q0 = __ldg(p + (size_t)(t + 8) * Ktag);
                step(q1, t + 1); q1 = __ldg(p + (size_t)(t + 9) * Ktag);
                step(q2, t + 2); q2 = __ldg(p + (size_t)(t + 10) * Ktag);
                step(q3, t + 3); q3 = __ldg(p + (size_t)(t + 11) * Ktag);
                step(q4, t + 4); q4 = __ldg(p + (size_t)(t + 12) * Ktag);
                step(q5, t + 5); q5 = __ldg(p + (size_t)(t + 13) * Ktag);
                step(q6, t + 6); q6 = __ldg(p + (size_t)(t + 14) * Ktag);
                step(q7, t + 7); q7 = __ldg(p + (size_t)(t + 15) * Ktag);
            }
#pragma unroll 1
            for (; t < L; ++t) step(__ldg(p + (size_t)t * Ktag), t);

            // final logsumexp over lanes
            float mm = alpha;
#pragma unroll
            for (int off = 16; off; off >>= 1)
                mm = fmaxf(mm, __shfl_xor_sync(FULLMASK, mm, off));
            float e = __expf(alpha - mm);
#pragma unroll
            for (int off = 16; off; off >>= 1)
                e += __shfl_xor_sync(FULLMASK, e, off);
            const float logNorm = mm + __logf(e);

            // sequence score + log-likelihood
            const int*   tg = tg_in + (size_t)b * Tlen;
            const float* p0 = pot + (size_t)b * Tlen * Ktag;
            float s = 0.f;
            for (int t2 = j; t2 < L; t2 += 32) {
                const int tt = tg[t2];
                s += __ldg(&p0[t2 * Ktag + tt]);
                if (t2 < L - 1) s += __ldg(&trans[tt * 32 + tg[t2 + 1]]);
            }
#pragma unroll
            for (int off = 16; off; off >>= 1)
                s += __shfl_xor_sync(FULLMASK, s, off);
            if (j == 0)
                out[(size_t)Bsz * Tlen + Bsz + b] = s - logNorm;
        }
    }
}

// ---------------------------------------------------------------------------
extern "C" void kernel_launch(void* const* d_in, const int* in_sizes, int n_in,
                              void* d_out, int out_size)
{
    const float* pot   = (const float*)d_in[0];
    const float* trans = (const float*)d_in[1];
    const int*   slen  = (const int*)d_in[2];
    const int*   tags  = (const int*)d_in[3];
    float*       out   = (float*)d_out;

    crf_sort<<<1, 1024>>>(slen);
    crf_main<<<Bsz, 32>>>(pot, trans, slen, tags, out);
}